// round 17
// baseline (speedup 1.0000x reference)
#include <cuda_runtime.h>
#include <cuda_fp16.h>
#include <cstdint>

// ---------------------------------------------------------------------------
// ChunkParallelGRU: B=64, T=512, D=1024, H=1024, CHUNK=4
//
//   pre[g][m][n] = x[m] @ Wg_x + bg          (fp16 2-term MMA GEMM)
//   per step t (sequential, persistent kernel, NB=64 blocks):
//     P1: z = sig(pre_z + h @ Wz_h)          -> g_z    (blocks 0..31, 32 cols)
//         rh = sig(pre_r + h @ Wr_h) * h     -> rh fp16 (blocks 32..63)
//     P2: cand = tanh(pre_h + rh @ Wh_h);  16 cols/block
//         h_new = h + z*(cand-h); out[t] = h_new
//     P3 (chunk boundary): h = tanh(h_new @ Wp + bp)
//
// v14 = v13 with NB 128 -> 64: total A-broadcast staging traffic HALVES
//       (18 MB/step), barrier max over 64 stragglers, P1 has no cross-warp
//       k-reduction (NT=4/KSEG=1). K-chunks 256 (4/phase) to fit smem.
// ---------------------------------------------------------------------------

#define BB 64
#define TT 512
#define BT (BB * 512)
#define NB 64           // persistent grid
#define THR 512

// Scratch (static device arrays; allocation-free)
__device__ float g_pre[(size_t)BT * 3072];            // [m][z|r|h]
__device__ float g_wt_all[(size_t)7168 * 1024];       // transposed fp32 weights
__device__ __half g_w16h[(size_t)7168 * 1024];        // fp16 hi: [zr_h|h_h|p|z_x|r_x|h_x]
__device__ __half g_w16l[(size_t)7168 * 1024];        // fp16 lo (used by pre GEMM)
__device__ __half g_x16[(size_t)BT * 1024];           // fp16 x
__device__ float g_hbuf[2][BB * 1024];                // fp32 state (epilogue reads)
__device__ __half g_h16[2][BB * 1024];                // fp16 state (MMA A)
__device__ __half g_rh16[BB * 1024];                  // fp16 sig(r)*h
__device__ float g_z[BB * 1024];                      // sigmoided z
__device__ unsigned g_ctr;                            // barrier counter (monotonic)

__device__ __forceinline__ float sig_(float x) {
    return 1.0f / (1.0f + __expf(-x));
}
__device__ __forceinline__ float tanh_(float x) {
    x = fminf(15.0f, fmaxf(-15.0f, x));
    float e = __expf(-2.0f * x);
    return (1.0f - e) / (1.0f + e);
}

// fp16 MMA: D(16x8,f32) += A(16x16,f16)*B(16x8,f16)
__device__ __forceinline__ void mma_f16(float* d, const unsigned* a, const unsigned* b) {
    asm volatile(
        "mma.sync.aligned.m16n8k16.row.col.f32.f16.f16.f32 "
        "{%0,%1,%2,%3}, {%4,%5,%6,%7}, {%8,%9}, {%0,%1,%2,%3};\n"
        : "+f"(d[0]), "+f"(d[1]), "+f"(d[2]), "+f"(d[3])
        : "r"(a[0]), "r"(a[1]), "r"(a[2]), "r"(a[3]), "r"(b[0]), "r"(b[1]));
}

// pack two floats to fp16x2 word (low = a, high = b)
__device__ __forceinline__ unsigned packh2(float a, float b) {
    __half2 p = __floats2half2_rn(a, b);
    return *reinterpret_cast<unsigned*>(&p);
}

// cp.async 16B via L2 (bypasses L1)
__device__ __forceinline__ void cpa16(uint32_t s, const void* g) {
    asm volatile("cp.async.cg.shared.global [%0], [%1], 16;" :: "r"(s), "l"(g) : "memory");
}
#define CP_COMMIT() asm volatile("cp.async.commit_group;" ::: "memory")

// ---------------------------------------------------------------------------
// Grid barrier (round-6, known good).
// ---------------------------------------------------------------------------
__device__ __forceinline__ void grid_barrier(unsigned ep) {
    __syncthreads();
    if (threadIdx.x == 0) {
        asm volatile("red.release.gpu.global.add.u32 [%0], 1;"
                     :: "l"(&g_ctr) : "memory");
        const unsigned target = ep * NB;
        unsigned v;
        do {
            asm volatile("ld.acquire.gpu.global.u32 %0, [%1];"
                         : "=r"(v) : "l"(&g_ctr) : "memory");
        } while ((int)(v - target) < 0);
    }
    __syncthreads();
}

// ---------------------------------------------------------------------------
// Weight transpose into unified array: g_wt_all[z*1024 + n][k] = src[off+k][n]
// ---------------------------------------------------------------------------
__global__ void transpose_weights(const float* __restrict__ Wz,
                                  const float* __restrict__ Wr,
                                  const float* __restrict__ Wh,
                                  const float* __restrict__ Wp) {
    __shared__ float tile[32][33];
    const int z = blockIdx.z;
    const float* src;
    int srcOff;
    switch (z) {
        case 0: src = Wz; srcOff = 1024; break;
        case 1: src = Wr; srcOff = 1024; break;
        case 2: src = Wh; srcOff = 1024; break;
        case 3: src = Wp; srcOff = 0;    break;
        case 4: src = Wz; srcOff = 0;    break;
        case 5: src = Wr; srcOff = 0;    break;
        default: src = Wh; srcOff = 0;   break;
    }
    float* dst = g_wt_all + (size_t)z * 1024 * 1024;
    const int kBase = blockIdx.x * 32;
    const int cBase = blockIdx.y * 32;
    tile[threadIdx.y][threadIdx.x] =
        src[(size_t)(srcOff + kBase + threadIdx.y) * 1024 + cBase + threadIdx.x];
    __syncthreads();
    dst[(size_t)(cBase + threadIdx.y) * 1024 + kBase + threadIdx.x] =
        tile[threadIdx.x][threadIdx.y];
}

__global__ void split_weights() {
    size_t i = (size_t)blockIdx.x * blockDim.x + threadIdx.x;
    if (i >= (size_t)7168 * 1024) return;
    float v = g_wt_all[i];
    __half h16 = __float2half_rn(v);
    g_w16h[i] = h16;
    g_w16l[i] = __float2half_rn(v - __half2float(h16));
}

__global__ void split_x(const float* __restrict__ x) {
    size_t i = (size_t)blockIdx.x * blockDim.x + threadIdx.x;
    if (i >= (size_t)BT * 1024) return;
    g_x16[i] = __float2half_rn(x[i]);
}

__global__ void init_h(const float* __restrict__ h0) {
    int i = blockIdx.x * blockDim.x + threadIdx.x;
    if (i == 0) g_ctr = 0u;
    if (i < BB * 1024) {
        float v = h0[i];
        g_hbuf[0][i] = v;
        g_h16[0][i] = __float2half_rn(v);
    }
}

// ---------------------------------------------------------------------------
// Precompute GEMM, fp16 (unchanged, round-15 proven).
// ---------------------------------------------------------------------------
#define SG_AST 40
#define SG_A   (128 * SG_AST)
#define SG_BUFE (3 * SG_A)
#define SG_SMEM_BYTES (2 * SG_BUFE * 2)

__global__ void __launch_bounds__(256, 1) sgemm_pre_mma(
    const float* __restrict__ bz, const float* __restrict__ br,
    const float* __restrict__ bh) {
    extern __shared__ __half sm[];
    const int gate = blockIdx.z;
    const int m0 = blockIdx.y * 128;
    const int n0 = blockIdx.x * 128;
    const float* bias = (gate == 0) ? bz : (gate == 1) ? br : bh;
    const size_t wrow = (size_t)(4096 + gate * 1024 + n0) * 1024;

    const int tid = threadIdx.x;
    const int w = tid >> 5, lane = tid & 31, g4 = lane >> 2, t = lane & 3;
    const int wm = (w & 3) * 32, wn = (w >> 2) * 64;
    const uint32_t smb = (uint32_t)__cvta_generic_to_shared(sm);

    float acc[2][8][4];
#pragma unroll
    for (int i = 0; i < 2; i++)
#pragma unroll
        for (int j = 0; j < 8; j++)
#pragma unroll
            for (int e = 0; e < 4; e++) acc[i][j][e] = 0.0f;

#pragma unroll
    for (int q = 0; q < 2; q++) {
        int pos = q * 256 + tid;
        int row = pos >> 2, ku = (pos & 3) * 8;
        uint32_t soff = (uint32_t)(row * SG_AST + ku) * 2;
        cpa16(smb + 0 * SG_A * 2 + soff, &g_x16[(size_t)(m0 + row) * 1024 + ku]);
        cpa16(smb + 1 * SG_A * 2 + soff, &g_w16h[wrow + (size_t)row * 1024 + ku]);
        cpa16(smb + 2 * SG_A * 2 + soff, &g_w16l[wrow + (size_t)row * 1024 + ku]);
    }
    CP_COMMIT();

    int buf = 0;
#pragma unroll 1
    for (int ch = 0; ch < 32; ch++) {
        const bool hasNext = (ch < 31);
        if (hasNext) {
            const int k0 = (ch + 1) * 32;
            const uint32_t b0 = smb + (uint32_t)((buf ^ 1) * SG_BUFE) * 2;
#pragma unroll
            for (int q = 0; q < 2; q++) {
                int pos = q * 256 + tid;
                int row = pos >> 2, ku = (pos & 3) * 8;
                uint32_t soff = (uint32_t)(row * SG_AST + ku) * 2;
                cpa16(b0 + 0 * SG_A * 2 + soff, &g_x16[(size_t)(m0 + row) * 1024 + k0 + ku]);
                cpa16(b0 + 1 * SG_A * 2 + soff, &g_w16h[wrow + (size_t)row * 1024 + k0 + ku]);
                cpa16(b0 + 2 * SG_A * 2 + soff, &g_w16l[wrow + (size_t)row * 1024 + k0 + ku]);
            }
            CP_COMMIT();
            asm volatile("cp.async.wait_group 1;" ::: "memory");
        } else {
            asm volatile("cp.async.wait_group 0;" ::: "memory");
        }
        __syncthreads();

        const __half* bb = sm + buf * SG_BUFE;
        const __half* AA = bb;
        const __half* BH = bb + SG_A;
        const __half* BL = bb + 2 * SG_A;
#pragma unroll
        for (int kf = 0; kf < 2; kf++) {
            const int koff = kf * 16 + 2 * t;
            unsigned a[2][4];
#pragma unroll
            for (int mi = 0; mi < 2; mi++) {
                int ra = (wm + mi * 16 + g4) * SG_AST + koff;
                a[mi][0] = *reinterpret_cast<const unsigned*>(&AA[ra]);
                a[mi][1] = *reinterpret_cast<const unsigned*>(&AA[ra + 8 * SG_AST]);
                a[mi][2] = *reinterpret_cast<const unsigned*>(&AA[ra + 8]);
                a[mi][3] = *reinterpret_cast<const unsigned*>(&AA[ra + 8 * SG_AST + 8]);
            }
#pragma unroll
            for (int nj = 0; nj < 8; nj++) {
                int rb = (wn + nj * 8 + g4) * SG_AST + koff;
                unsigned bhi[2], blo[2];
                bhi[0] = *reinterpret_cast<const unsigned*>(&BH[rb]);
                bhi[1] = *reinterpret_cast<const unsigned*>(&BH[rb + 8]);
                blo[0] = *reinterpret_cast<const unsigned*>(&BL[rb]);
                blo[1] = *reinterpret_cast<const unsigned*>(&BL[rb + 8]);
#pragma unroll
                for (int mi = 0; mi < 2; mi++) {
                    mma_f16(acc[mi][nj], a[mi], bhi);
                    mma_f16(acc[mi][nj], a[mi], blo);
                }
            }
        }
        __syncthreads();
        buf ^= 1;
    }

#pragma unroll
    for (int nj = 0; nj < 8; nj++) {
        int c = n0 + wn + nj * 8 + 2 * t;
        float b0v = bias[c], b1v = bias[c + 1];
#pragma unroll
        for (int mi = 0; mi < 2; mi++) {
            int r = m0 + wm + mi * 16 + g4;
            float2 o0 = make_float2(acc[mi][nj][0] + b0v, acc[mi][nj][1] + b1v);
            float2 o1 = make_float2(acc[mi][nj][2] + b0v, acc[mi][nj][3] + b1v);
            *reinterpret_cast<float2*>(&g_pre[(size_t)r * 3072 + gate * 1024 + c]) = o0;
            *reinterpret_cast<float2*>(&g_pre[(size_t)(r + 8) * 3072 + gate * 1024 + c]) = o1;
        }
    }
}

// ---------------------------------------------------------------------------
// Recurrent SMEM layout (NB=64): W = 64 cols fp16, A in K=256 chunks x2.
//   AST2=264 fp16 (528 B = 132 words == 4 mod 32: conflict-free, proven).
// ---------------------------------------------------------------------------
#define AST2 264
#define ACH  (64 * AST2)                  // 16896 fp16
#define WST2 1032
#define SM_W     0                        // 64*1032*2 = 132096
#define SM_A     132096                   // 2*ACH*2   = 67584
#define SM_RED   199680                   // float[1024] = 4096
#define SM_TOTAL 203776

// ---------------------------------------------------------------------------
// fp16 MMA tile, single W term: C(64 x NT*8) = A16 @ W16.
// 16 warps: mi=w>>2, ni=(w&3)/KSEG, ks=w&(KSEG-1). K-chunks 256, double
// buffered, rotated staging. KSEG=1: no cross-warp reduce at all.
// ---------------------------------------------------------------------------
template <int NT, int KSEG>
__device__ __forceinline__ void mma_tile16(const __half* __restrict__ AG,
                                           const __half* __restrict__ WS,
                                           int colBase,
                                           __half* __restrict__ AS,
                                           float* __restrict__ red,
                                           float* __restrict__ d, int tid, int bid) {
    const int w = tid >> 5, lane = tid & 31;
    const int g = lane >> 2, t = lane & 3;
    const int mi = w >> 2;
    const int ni = (w & 3) / KSEG;
    const int ks = w & (KSEG - 1);
    const int SEGK = 256 / KSEG;
    const uint32_t as_b = (uint32_t)__cvta_generic_to_shared(AS);
    const int shift = bid << 5;   // rotated staging (anti-lockstep)

    float da[4] = {0.f, 0.f, 0.f, 0.f};
    float db[4] = {0.f, 0.f, 0.f, 0.f};

    // prologue: chunk 0 -> buf 0 (64 rows x 256 k fp16 = 2048 x 16B; 4/thread)
#pragma unroll
    for (int p = 0; p < 4; p++) {
        int pos = (p * 512 + tid + shift) & 2047;
        int row = pos >> 5, ku = (pos & 31) << 3;
        cpa16(as_b + (uint32_t)(row * AST2 + ku) * 2, &AG[row * 1024 + ku]);
    }
    CP_COMMIT();

    int buf = 0;
#pragma unroll 1
    for (int ch = 0; ch < 4; ch++) {
        if (ch < 3) {
            const int kb = (ch + 1) << 8;
            const uint32_t bb = as_b + (uint32_t)((buf ^ 1) * ACH) * 2;
#pragma unroll
            for (int p = 0; p < 4; p++) {
                int pos = (p * 512 + tid + shift) & 2047;
                int row = pos >> 5, ku = (pos & 31) << 3;
                cpa16(bb + (uint32_t)(row * AST2 + ku) * 2, &AG[row * 1024 + kb + ku]);
            }
            CP_COMMIT();
            asm volatile("cp.async.wait_group 1;" ::: "memory");
        } else {
            asm volatile("cp.async.wait_group 0;" ::: "memory");
        }
        __syncthreads();

        const __half* AH = AS + buf * ACH;
        const int ar = (mi * 16 + g) * AST2 + ks * SEGK + 2 * t;
        const int wr = (colBase + ni * 8 + g) * WST2 + (ch << 8) + ks * SEGK + 2 * t;
#pragma unroll
        for (int j = 0; j < SEGK / 16; j++) {
            const int ka = ar + j * 16;
            const int kw = wr + j * 16;
            unsigned a[4], bw[2];
            a[0] = *reinterpret_cast<const unsigned*>(&AH[ka]);
            a[1] = *reinterpret_cast<const unsigned*>(&AH[ka + 8 * AST2]);
            a[2] = *reinterpret_cast<const unsigned*>(&AH[ka + 8]);
            a[3] = *reinterpret_cast<const unsigned*>(&AH[ka + 8 * AST2 + 8]);
            bw[0] = *reinterpret_cast<const unsigned*>(&WS[kw]);
            bw[1] = *reinterpret_cast<const unsigned*>(&WS[kw + 8]);
            mma_f16((j & 1) ? db : da, a, bw);
        }
        __syncthreads();
        buf ^= 1;
    }

#pragma unroll
    for (int e = 0; e < 4; e++) d[e] = da[e] + db[e];

    // reduce k-segments (only when KSEG > 1)
    if (KSEG > 1) {
        if (ks != 0) {
            float* dst = red + (((mi * NT + ni) * (KSEG - 1) + (ks - 1)) * 32 + lane) * 4;
            dst[0] = d[0]; dst[1] = d[1]; dst[2] = d[2]; dst[3] = d[3];
        }
        __syncthreads();
        if (ks == 0) {
#pragma unroll
            for (int s = 0; s < KSEG - 1; s++) {
                const float* src = red + (((mi * NT + ni) * (KSEG - 1) + s) * 32 + lane) * 4;
                d[0] += src[0]; d[1] += src[1]; d[2] += src[2]; d[3] += src[3];
            }
        }
    }
}

// ---------------------------------------------------------------------------
// Persistent recurrent kernel: 64 blocks x 512 threads, 512 steps.
// ---------------------------------------------------------------------------
__global__ void __launch_bounds__(THR, 1) gru_recurrent(const float* __restrict__ bp,
                                                        float* __restrict__ out) {
    extern __shared__ char smem[];
    __half* WS  = reinterpret_cast<__half*>(smem + SM_W);
    __half* AS  = reinterpret_cast<__half*>(smem + SM_A);
    float*  red = reinterpret_cast<float*>(smem + SM_RED);

    const int tid = threadIdx.x;
    const int bid = blockIdx.x;
    const int w = tid >> 5, lane = tid & 31;
    const int g = lane >> 2, t = lane & 3;

    // Load this block's 64 weight columns (fp16) into SMEM once.
    // cols 0-31: zr cols bid*32+i ; 32-47: h cols bid*16+(i-32) ;
    // 48-63: p cols bid*16+(i-48).
    for (int idx = tid; idx < 64 * 128; idx += THR) {
        int i = idx >> 7, ko = (idx & 127) << 3;
        int gc = (i < 32) ? (bid * 32 + i)
               : (i < 48) ? (2048 + bid * 16 + (i - 32))
                          : (3072 + bid * 16 + (i - 48));
        *reinterpret_cast<uint4*>(&WS[i * WST2 + ko]) =
            *reinterpret_cast<const uint4*>(&g_w16h[(size_t)gc * 1024 + ko]);
    }
    __syncthreads();

    const bool isR = (bid >= 32);   // P1 r-half (cols 1024..2047)
    unsigned ep = 0;
    int p = 0;   // h lives in buffers [p] at step start

#pragma unroll 1
    for (int tt = 0; tt < TT; tt++) {
        const float* h = g_hbuf[p];

        // ---- phase 1 (32 cols/block, NT=4/KSEG=1, all warps valid) ----
        {
            const int mi = w >> 2, ni = w & 3;
            const int cz = (bid << 5) + ni * 8 + 2 * t;
            const int r0 = mi * 16 + g, r1 = r0 + 8;
            // prefetch epilogue operands
            float p00 = __ldcs(&g_pre[(size_t)(r0 * TT + tt) * 3072 + cz]);
            float p01 = __ldcs(&g_pre[(size_t)(r0 * TT + tt) * 3072 + cz + 1]);
            float p10 = __ldcs(&g_pre[(size_t)(r1 * TT + tt) * 3072 + cz]);
            float p11 = __ldcs(&g_pre[(size_t)(r1 * TT + tt) * 3072 + cz + 1]);
            float h00 = 0.f, h01 = 0.f, h10 = 0.f, h11 = 0.f;
            if (isR) {
                const int cn = cz - 1024;
                h00 = __ldcg(&h[r0 * 1024 + cn]);
                h01 = __ldcg(&h[r0 * 1024 + cn + 1]);
                h10 = __ldcg(&h[r1 * 1024 + cn]);
                h11 = __ldcg(&h[r1 * 1024 + cn + 1]);
            }
            float d[4];
            mma_tile16<4, 1>(g_h16[p], WS, 0, AS, red, d, tid, bid);
            float v00 = sig_(d[0] + p00);
            float v01 = sig_(d[1] + p01);
            float v10 = sig_(d[2] + p10);
            float v11 = sig_(d[3] + p11);
            if (isR) {
                const int cn = cz - 1024;
                __stcg(reinterpret_cast<unsigned*>(&g_rh16[r0 * 1024 + cn]),
                       packh2(v00 * h00, v01 * h01));
                __stcg(reinterpret_cast<unsigned*>(&g_rh16[r1 * 1024 + cn]),
                       packh2(v10 * h10, v11 * h11));
            } else {
                __stcg(&g_z[r0 * 1024 + cz],     v00);
                __stcg(&g_z[r0 * 1024 + cz + 1], v01);
                __stcg(&g_z[r1 * 1024 + cz],     v10);
                __stcg(&g_z[r1 * 1024 + cz + 1], v11);
            }
        }
        grid_barrier(++ep);

        // ---- phase 2 (16 cols/block, NT=2/KSEG=2, even warps valid) ----
        const int pn = p ^ 1;
        {
            const int mi = w >> 2, ni = (w & 3) >> 1;
            const int c0 = (bid << 4) + ni * 8 + 2 * t;
            const int r0 = mi * 16 + g, r1 = r0 + 8;
            float ph00 = 0.f, ph01 = 0.f, ph10 = 0.f, ph11 = 0.f;
            float z00 = 0.f, z01 = 0.f, z10 = 0.f, z11 = 0.f;
            float h00 = 0.f, h01 = 0.f, h10 = 0.f, h11 = 0.f;
            if ((w & 1) == 0) {   // prefetch epilogue operands
                ph00 = __ldcs(&g_pre[(size_t)(r0 * TT + tt) * 3072 + 2048 + c0]);
                ph01 = __ldcs(&g_pre[(size_t)(r0 * TT + tt) * 3072 + 2048 + c0 + 1]);
                ph10 = __ldcs(&g_pre[(size_t)(r1 * TT + tt) * 3072 + 2048 + c0]);
                ph11 = __ldcs(&g_pre[(size_t)(r1 * TT + tt) * 3072 + 2048 + c0 + 1]);
                z00 = __ldcg(&g_z[r0 * 1024 + c0]);
                z01 = __ldcg(&g_z[r0 * 1024 + c0 + 1]);
                z10 = __ldcg(&g_z[r1 * 1024 + c0]);
                z11 = __ldcg(&g_z[r1 * 1024 + c0 + 1]);
                h00 = __ldcg(&h[r0 * 1024 + c0]);
                h01 = __ldcg(&h[r0 * 1024 + c0 + 1]);
                h10 = __ldcg(&h[r1 * 1024 + c0]);
                h11 = __ldcg(&h[r1 * 1024 + c0 + 1]);
            }
            float d[4];
            mma_tile16<2, 2>(g_rh16, WS, 32, AS, red, d, tid, bid);
            if ((w & 1) == 0) {
                float hn00 = fmaf(z00, tanh_(d[0] + ph00) - h00, h00);
                float hn01 = fmaf(z01, tanh_(d[1] + ph01) - h01, h01);
                float hn10 = fmaf(z10, tanh_(d[2] + ph10) - h10, h10);
                float hn11 = fmaf(z11, tanh_(d[3] + ph11) - h11, h11);
                out[(size_t)(r0 * TT + tt) * 1024 + c0]     = hn00;
                out[(size_t)(r0 * TT + tt) * 1024 + c0 + 1] = hn01;
                out[(size_t)(r1 * TT + tt) * 1024 + c0]     = hn10;
                out[(size_t)(r1 * TT + tt) * 1024 + c0 + 1] = hn11;
                __stcg(&g_hbuf[pn][r0 * 1024 + c0],     hn00);
                __stcg(&g_hbuf[pn][r0 * 1024 + c0 + 1], hn01);
                __stcg(&g_hbuf[pn][r1 * 1024 + c0],     hn10);
                __stcg(&g_hbuf[pn][r1 * 1024 + c0 + 1], hn11);
                __stcg(reinterpret_cast<unsigned*>(&g_h16[pn][r0 * 1024 + c0]),
                       packh2(hn00, hn01));
                __stcg(reinterpret_cast<unsigned*>(&g_h16[pn][r1 * 1024 + c0]),
                       packh2(hn10, hn11));
            }
        }
        grid_barrier(++ep);

        // ---- phase 3: chunk-boundary projection (16 cols/block) ----
        const bool prop = ((tt & 3) == 3) && (tt != TT - 1);
        if (prop) {
            float d[4];
            mma_tile16<2, 2>(g_h16[pn], WS, 48, AS, red, d, tid, bid);
            if ((w & 1) == 0) {
                const int mi = w >> 2, ni = (w & 3) >> 1;
                const int c0 = (bid << 4) + ni * 8 + 2 * t;
                const int r0 = mi * 16 + g, r1 = r0 + 8;
                float bp0 = bp[c0], bp1 = bp[c0 + 1];
                float v00 = tanh_(d[0] + bp0);
                float v01 = tanh_(d[1] + bp1);
                float v10 = tanh_(d[2] + bp0);
                float v11 = tanh_(d[3] + bp1);
                __stcg(&g_hbuf[p][r0 * 1024 + c0],     v00);
                __stcg(&g_hbuf[p][r0 * 1024 + c0 + 1], v01);
                __stcg(&g_hbuf[p][r1 * 1024 + c0],     v10);
                __stcg(&g_hbuf[p][r1 * 1024 + c0 + 1], v11);
                __stcg(reinterpret_cast<unsigned*>(&g_h16[p][r0 * 1024 + c0]),
                       packh2(v00, v01));
                __stcg(reinterpret_cast<unsigned*>(&g_h16[p][r1 * 1024 + c0]),
                       packh2(v10, v11));
            }
            grid_barrier(++ep);
            // h stays in buffers [p]
        } else {
            p ^= 1;
        }
    }
}

// ---------------------------------------------------------------------------
extern "C" void kernel_launch(void* const* d_in, const int* in_sizes, int n_in,
                              void* d_out, int out_size) {
    (void)in_sizes; (void)n_in; (void)out_size;
    const float* x  = (const float*)d_in[0];
    const float* h0 = (const float*)d_in[1];
    const float* Wz = (const float*)d_in[2];
    const float* bz = (const float*)d_in[3];
    const float* Wr = (const float*)d_in[4];
    const float* br = (const float*)d_in[5];
    const float* Wh = (const float*)d_in[6];
    const float* bh = (const float*)d_in[7];
    const float* Wp = (const float*)d_in[8];
    const float* bp = (const float*)d_in[9];
    float* out = (float*)d_out;

    static bool attr_set = false;
    if (!attr_set) {
        cudaFuncSetAttribute(gru_recurrent, cudaFuncAttributeMaxDynamicSharedMemorySize,
                             SM_TOTAL);
        cudaFuncSetAttribute(sgemm_pre_mma, cudaFuncAttributeMaxDynamicSharedMemorySize,
                             SG_SMEM_BYTES);
        attr_set = true;
    }

    transpose_weights<<<dim3(32, 32, 7), dim3(32, 32)>>>(Wz, Wr, Wh, Wp);
    split_weights<<<14336, 512>>>();
    split_x<<<65536, 512>>>(x);
    init_h<<<64, 1024>>>(h0);
    sgemm_pre_mma<<<dim3(8, 256, 3), 256, SG_SMEM_BYTES>>>(bz, br, bh);
    gru_recurrent<<<NB, THR, SM_TOTAL>>>(bp, out);
}